// round 2
// baseline (speedup 1.0000x reference)
#include <cuda_runtime.h>
#include <cuda_bf16.h>
#include <math.h>

// Problem constants
#define Bb 4
#define Tt 2048
#define Dd 2048
#define Hh 16
#define Gg 4
#define Kk 128
#define Rr 4          // H / G
#define EPS 1e-6f
#define ROPE_BASE 10000.0f
#define SOFTMAX_SCALE 0.08838834764831845f  // K^-0.5

#define MTOT (Bb * Tt)          // 8192 rows

// --------------------------- scratch (device globals; no mallocs) ------------
__device__ float g_q[(size_t)MTOT * Hh * Kk];     // 64 MB
__device__ float g_k[(size_t)MTOT * Gg * Kk];     // 16 MB
__device__ float g_v[(size_t)MTOT * Gg * Kk];     // 16 MB
__device__ float g_attn[(size_t)MTOT * Hh * Kk];  // 64 MB
__device__ int   g_pos[MTOT];

// --------------------------- SGEMM: C[M,N] = A[M,Kd] @ B[Kd,N] ---------------
// 128x128 tile, BK=8, 256 threads, 8x8 per thread, fp32 FMA.
// Requires M%128==0, N%128==0, Kd%8==0 (true for all our shapes).
#define BM 128
#define BN 128
#define BK 8
#define TM 8
#define TN 8

__global__ __launch_bounds__(256, 2)
void sgemm_kernel(int M, int N, int Kd,
                  const float* __restrict__ A,
                  const float* __restrict__ B,
                  float* __restrict__ C) {
    __shared__ float As[BK][BM];
    __shared__ float Bs[BK][BN];

    const int tid  = threadIdx.x;
    const int cRow = blockIdx.y;
    const int cCol = blockIdx.x;

    A += (size_t)cRow * BM * Kd;
    B += (size_t)cCol * BN;
    C += (size_t)cRow * BM * N + (size_t)cCol * BN;

    // A tile load: 128 rows x 8 cols = 1024 floats; one float4 per thread
    const int aRow = tid >> 1;           // 0..127
    const int aCol = (tid & 1) * 4;      // 0 or 4
    // B tile load: 8 rows x 128 cols; one float4 per thread
    const int bRow = tid >> 5;           // 0..7
    const int bCol = (tid & 31) * 4;     // 0..124

    const int ty = (tid / 16) * TM;
    const int tx = (tid % 16) * TN;

    float acc[TM][TN];
#pragma unroll
    for (int i = 0; i < TM; i++)
#pragma unroll
        for (int j = 0; j < TN; j++) acc[i][j] = 0.f;

    float rA[TM], rB[TN];

    for (int k0 = 0; k0 < Kd; k0 += BK) {
        float4 a4 = *(const float4*)(A + (size_t)aRow * Kd + k0 + aCol);
        As[aCol + 0][aRow] = a4.x;
        As[aCol + 1][aRow] = a4.y;
        As[aCol + 2][aRow] = a4.z;
        As[aCol + 3][aRow] = a4.w;
        float4 b4 = *(const float4*)(B + (size_t)(k0 + bRow) * N + bCol);
        *(float4*)&Bs[bRow][bCol] = b4;
        __syncthreads();

#pragma unroll
        for (int kk = 0; kk < BK; kk++) {
#pragma unroll
            for (int i = 0; i < TM; i++) rA[i] = As[kk][ty + i];
#pragma unroll
            for (int j = 0; j < TN; j++) rB[j] = Bs[kk][tx + j];
#pragma unroll
            for (int i = 0; i < TM; i++)
#pragma unroll
                for (int j = 0; j < TN; j++)
                    acc[i][j] = fmaf(rA[i], rB[j], acc[i][j]);
        }
        __syncthreads();
    }

#pragma unroll
    for (int i = 0; i < TM; i++)
#pragma unroll
        for (int j = 0; j < TN; j += 4) {
            float4 o = make_float4(acc[i][j], acc[i][j + 1], acc[i][j + 2], acc[i][j + 3]);
            *(float4*)(C + (size_t)(ty + i) * N + tx + j) = o;
        }
}

// --------------------------- positions from sorted segment ids ---------------
__global__ void pos_kernel(const int* __restrict__ seg, int* __restrict__ pos) {
    int idx = blockIdx.x * blockDim.x + threadIdx.x;
    if (idx >= MTOT) return;
    int b = idx / Tt;
    int t = idx % Tt;
    const int* row = seg + (size_t)b * Tt;
    int s = row[t];
    // lower_bound on sorted row -> first index of this segment value
    int lo = 0, hi = t;
    while (lo < hi) {
        int mid = (lo + hi) >> 1;
        if (row[mid] < s) lo = mid + 1; else hi = mid;
    }
    pos[idx] = t - lo;
}

// --------------------------- fused RMSNorm + RoPE (in place) -----------------
// One 128-thread block per head vector. NH = H for q, G for k.
__global__ __launch_bounds__(128)
void rms_rope_kernel(float* __restrict__ x, const float* __restrict__ scale,
                     const int* __restrict__ pos, int NH) {
    const int bt = blockIdx.x / NH;
    const int h  = blockIdx.x % NH;
    float* p = x + ((size_t)bt * NH + h) * Kk;

    const int i = threadIdx.x;
    float v = p[i];

    __shared__ float red[4];
    __shared__ float sx[Kk];
    float sq = v * v;
#pragma unroll
    for (int o = 16; o; o >>= 1) sq += __shfl_xor_sync(0xffffffffu, sq, o);
    if ((i & 31) == 0) red[i >> 5] = sq;
    __syncthreads();
    float var = (red[0] + red[1] + red[2] + red[3]) * (1.0f / Kk);
    float xn  = v * rsqrtf(var + EPS) * scale[i];
    sx[i] = xn;
    __syncthreads();

    if (i < Kk / 2) {
        float x1 = sx[i];
        float x2 = sx[i + Kk / 2];
        float pp = (float)pos[bt];
        // inv_freq = exp(-ln(base) * 2i/K)
        float inv = expf(-logf(ROPE_BASE) * (2.0f * (float)i / (float)Kk));
        float ang = pp * inv;
        float s, c;
        sincosf(ang, &s, &c);
        p[i]           = x1 * c - x2 * s;
        p[i + Kk / 2]  = x2 * c + x1 * s;
    }
}

// --------------------------- attention: warp per (b,t,h) ---------------------
// Key window is contiguous: s in [t - pos[t], t] (causal AND same-segment,
// because segment_ids are sorted => segments are contiguous runs).
__global__ __launch_bounds__(256)
void attn_kernel(const float* __restrict__ q, const float* __restrict__ k,
                 const float* __restrict__ v, const int* __restrict__ pos,
                 float* __restrict__ out) {
    const int warp = threadIdx.x >> 5;
    const int lane = threadIdx.x & 31;
    const long gw = (long)blockIdx.x * 8 + warp;   // global warp id
    // gw in [0, B*T*H)
    const int b = (int)(gw / ((long)Tt * Hh));
    const int rem = (int)(gw % ((long)Tt * Hh));
    const int t = rem / Hh;
    const int h = rem % Hh;
    const int g = h / Rr;

    const float* qp = q + (((size_t)b * Tt + t) * Hh + h) * Kk;
    float q0 = qp[lane];
    float q1 = qp[lane + 32];
    float q2 = qp[lane + 64];
    float q3 = qp[lane + 96];

    const int p  = pos[b * Tt + t];
    const int s0 = t - p;

    float m = -INFINITY, l = 0.f;
    float a0 = 0.f, a1 = 0.f, a2 = 0.f, a3 = 0.f;

    const float* kbase = k + ((size_t)b * Tt * Gg + g) * Kk;
    const float* vbase = v + ((size_t)b * Tt * Gg + g) * Kk;

    for (int s = s0; s <= t; ++s) {
        const float* kp = kbase + (size_t)s * Gg * Kk;
        float sc = q0 * kp[lane] + q1 * kp[lane + 32]
                 + q2 * kp[lane + 64] + q3 * kp[lane + 96];
#pragma unroll
        for (int o = 16; o; o >>= 1) sc += __shfl_xor_sync(0xffffffffu, sc, o);
        sc *= SOFTMAX_SCALE;

        float mn   = fmaxf(m, sc);
        float corr = __expf(m - mn);      // 0 on first iter (m = -inf)
        float pe   = __expf(sc - mn);
        l = l * corr + pe;

        const float* vp = vbase + (size_t)s * Gg * Kk;
        a0 = a0 * corr + pe * vp[lane];
        a1 = a1 * corr + pe * vp[lane + 32];
        a2 = a2 * corr + pe * vp[lane + 64];
        a3 = a3 * corr + pe * vp[lane + 96];
        m = mn;
    }

    float inv = 1.0f / l;
    float* op = out + (((size_t)b * Tt + t) * Hh + h) * Kk;
    op[lane]      = a0 * inv;
    op[lane + 32] = a1 * inv;
    op[lane + 64] = a2 * inv;
    op[lane + 96] = a3 * inv;
}

// --------------------------- launch --------------------------------------
extern "C" void kernel_launch(void* const* d_in, const int* in_sizes, int n_in,
                              void* d_out, int out_size) {
    const float* hidden = (const float*)d_in[0];
    const float* wq     = (const float*)d_in[1];
    const float* wk     = (const float*)d_in[2];
    const float* wv     = (const float*)d_in[3];
    const float* wo     = (const float*)d_in[4];
    const float* q_scale = (const float*)d_in[5];
    const float* k_scale = (const float*)d_in[6];
    const int*   seg    = (const int*)d_in[7];
    float* out = (float*)d_out;

    float *qb, *kb, *vb, *ab;
    int* posb;
    cudaGetSymbolAddress((void**)&qb, g_q);
    cudaGetSymbolAddress((void**)&kb, g_k);
    cudaGetSymbolAddress((void**)&vb, g_v);
    cudaGetSymbolAddress((void**)&ab, g_attn);
    cudaGetSymbolAddress((void**)&posb, g_pos);

    // 1) QKV projections
    {
        dim3 blk(256);
        dim3 grdQ((Hh * Kk) / BN, MTOT / BM);
        sgemm_kernel<<<grdQ, blk>>>(MTOT, Hh * Kk, Dd, hidden, wq, qb);
        dim3 grdK((Gg * Kk) / BN, MTOT / BM);
        sgemm_kernel<<<grdK, blk>>>(MTOT, Gg * Kk, Dd, hidden, wk, kb);
        sgemm_kernel<<<grdK, blk>>>(MTOT, Gg * Kk, Dd, hidden, wv, vb);
    }

    // 2) positions
    pos_kernel<<<(MTOT + 255) / 256, 256>>>(seg, posb);

    // 3) RMSNorm + RoPE (in place) on q and k
    rms_rope_kernel<<<MTOT * Hh, 128>>>(qb, q_scale, posb, Hh);
    rms_rope_kernel<<<MTOT * Gg, 128>>>(kb, k_scale, posb, Gg);

    // 4) attention: one warp per (b,t,h)
    {
        long total_warps = (long)MTOT * Hh;          // 131072
        int blocks = (int)(total_warps / 8);
        attn_kernel<<<blocks, 256>>>(qb, kb, vb, posb, ab);
    }

    // 5) output projection
    {
        dim3 blk(256);
        dim3 grd(Dd / BN, MTOT / BM);
        sgemm_kernel<<<grd, blk>>>(MTOT, Dd, Hh * Kk, ab, wo, out);
    }
}

// round 4
// speedup vs baseline: 2.1688x; 2.1688x over previous
#include <cuda_runtime.h>
#include <cuda_bf16.h>
#include <math.h>
#include <stdint.h>

// Problem constants
#define Bb 4
#define Tt 2048
#define Dd 2048
#define Hh 16
#define Gg 4
#define Kk 128
#define Rr 4          // H / G
#define EPS 1e-6f
#define ROPE_BASE 10000.0f
#define SOFTMAX_SCALE 0.08838834764831845f  // K^-0.5

#define MTOT (Bb * Tt)          // 8192 rows

// --------------------------- scratch (device globals; no mallocs) ------------
__device__ float g_q[(size_t)MTOT * Hh * Kk];     // 64 MB
__device__ float g_k[(size_t)MTOT * Gg * Kk];     // 16 MB
__device__ float g_v[(size_t)MTOT * Gg * Kk];     // 16 MB
__device__ float g_attn[(size_t)MTOT * Hh * Kk];  // 64 MB
__device__ int   g_pos[MTOT];

// =============================================================================
// TF32 tensor-core GEMM:  C[M,N] = A[M,Kd] @ B[Kd,N]   (all row-major fp32)
// CTA tile 128x128, BK=32, 256 threads (8 warps, 2x4 warp grid, warp tile 64x32)
// mma.sync.aligned.m16n8k8.row.col.f32.tf32.tf32.f32, cp.async double buffering.
// Requires M%128==0, N%128==0, Kd%32==0.
// =============================================================================
#define A_STRIDE 36            // 128 rows x 36  (pad 4) -> conflict-free A frags
#define B_STRIDE 136           // 32 rows x 136  (pad 8) -> conflict-free B frags
#define A_SZ (128 * A_STRIDE)  // floats per buffer
#define B_SZ (32 * B_STRIDE)
#define GEMM_SMEM_BYTES ((2 * A_SZ + 2 * B_SZ) * 4)   // 71680 B

__device__ __forceinline__ uint32_t f2tf32(float x) {
    uint32_t u;
    asm("cvt.rna.tf32.f32 %0, %1;" : "=r"(u) : "f"(x));
    return u;
}

__global__ __launch_bounds__(256)
void gemm_tf32_kernel(int M, int N, int Kd,
                      const float* __restrict__ A,
                      const float* __restrict__ B,
                      float* __restrict__ C) {
    extern __shared__ float sm[];
    float* As = sm;               // [2][128][A_STRIDE]
    float* Bsm = sm + 2 * A_SZ;   // [2][32][B_STRIDE]

    const int tid  = threadIdx.x;
    const int lane = tid & 31;
    const int wid  = tid >> 5;
    const int warpM = wid & 1;    // 0..1 (64 rows each)
    const int warpN = wid >> 1;   // 0..3 (32 cols each)

    const float* Ag = A + (size_t)blockIdx.y * 128 * Kd;
    const float* Bg = B + (size_t)blockIdx.x * 128;

    const uint32_t as_base = (uint32_t)__cvta_generic_to_shared(As);
    const uint32_t bs_base = (uint32_t)__cvta_generic_to_shared(Bsm);

    float acc[4][4][4];
#pragma unroll
    for (int i = 0; i < 4; i++)
#pragma unroll
        for (int j = 0; j < 4; j++)
#pragma unroll
            for (int r = 0; r < 4; r++) acc[i][j][r] = 0.f;

    auto issue_loads = [&](int buf, int k0) {
        // A tile: 128 x 32 floats, 1024 float4, 4 per thread
#pragma unroll
        for (int i = 0; i < 4; i++) {
            int idx = tid + i * 256;
            int r = idx >> 3, c = (idx & 7) * 4;
            uint32_t dst = as_base + (uint32_t)(buf * A_SZ + r * A_STRIDE + c) * 4u;
            const float* src = Ag + (size_t)r * Kd + k0 + c;
            asm volatile("cp.async.cg.shared.global [%0], [%1], 16;\n"
                         :: "r"(dst), "l"(src));
        }
        // B tile: 32 x 128 floats
#pragma unroll
        for (int i = 0; i < 4; i++) {
            int idx = tid + i * 256;
            int r = idx >> 5, c = (idx & 31) * 4;
            uint32_t dst = bs_base + (uint32_t)(buf * B_SZ + r * B_STRIDE + c) * 4u;
            const float* src = Bg + (size_t)(k0 + r) * N + c;
            asm volatile("cp.async.cg.shared.global [%0], [%1], 16;\n"
                         :: "r"(dst), "l"(src));
        }
        asm volatile("cp.async.commit_group;\n");
    };

    issue_loads(0, 0);
    const int KT = Kd >> 5;
    const int fr = lane >> 2;   // 0..7
    const int fc = lane & 3;    // 0..3

    for (int kt = 0; kt < KT; kt++) {
        asm volatile("cp.async.wait_group 0;\n");
        __syncthreads();
        const int cur = kt & 1;
        if (kt + 1 < KT) issue_loads(cur ^ 1, (kt + 1) << 5);

        const float* sA = As + cur * A_SZ;
        const float* sB = Bsm + cur * B_SZ;

#pragma unroll
        for (int kk = 0; kk < 4; kk++) {
            uint32_t af[4][4];
            uint32_t bf[4][2];
#pragma unroll
            for (int mt = 0; mt < 4; mt++) {
                const float* p = sA + (warpM * 64 + mt * 16 + fr) * A_STRIDE + kk * 8 + fc;
                af[mt][0] = f2tf32(p[0]);
                af[mt][1] = f2tf32(p[8 * A_STRIDE]);
                af[mt][2] = f2tf32(p[4]);
                af[mt][3] = f2tf32(p[8 * A_STRIDE + 4]);
            }
#pragma unroll
            for (int nt = 0; nt < 4; nt++) {
                const float* p = sB + (kk * 8 + fc) * B_STRIDE + warpN * 32 + nt * 8 + fr;
                bf[nt][0] = f2tf32(p[0]);
                bf[nt][1] = f2tf32(p[4 * B_STRIDE]);
            }
#pragma unroll
            for (int mt = 0; mt < 4; mt++)
#pragma unroll
                for (int nt = 0; nt < 4; nt++) {
                    asm volatile(
                        "mma.sync.aligned.m16n8k8.row.col.f32.tf32.tf32.f32 "
                        "{%0,%1,%2,%3}, {%4,%5,%6,%7}, {%8,%9}, {%0,%1,%2,%3};\n"
                        : "+f"(acc[mt][nt][0]), "+f"(acc[mt][nt][1]),
                          "+f"(acc[mt][nt][2]), "+f"(acc[mt][nt][3])
                        : "r"(af[mt][0]), "r"(af[mt][1]), "r"(af[mt][2]), "r"(af[mt][3]),
                          "r"(bf[nt][0]), "r"(bf[nt][1]));
                }
        }
        __syncthreads();
    }

    // Epilogue
    float* Cg = C + (size_t)blockIdx.y * 128 * N + (size_t)blockIdx.x * 128;
#pragma unroll
    for (int mt = 0; mt < 4; mt++) {
#pragma unroll
        for (int nt = 0; nt < 4; nt++) {
            int row = warpM * 64 + mt * 16 + fr;
            int col = warpN * 32 + nt * 8 + fc * 2;
            *(float2*)(Cg + (size_t)row * N + col) =
                make_float2(acc[mt][nt][0], acc[mt][nt][1]);
            *(float2*)(Cg + (size_t)(row + 8) * N + col) =
                make_float2(acc[mt][nt][2], acc[mt][nt][3]);
        }
    }
}

// --------------------------- positions from sorted segment ids ---------------
__global__ void pos_kernel(const int* __restrict__ seg, int* __restrict__ pos) {
    int idx = blockIdx.x * blockDim.x + threadIdx.x;
    if (idx >= MTOT) return;
    int b = idx / Tt;
    int t = idx % Tt;
    const int* row = seg + (size_t)b * Tt;
    int s = row[t];
    int lo = 0, hi = t;
    while (lo < hi) {
        int mid = (lo + hi) >> 1;
        if (row[mid] < s) lo = mid + 1; else hi = mid;
    }
    pos[idx] = t - lo;
}

// --------------------------- fused RMSNorm + RoPE (in place) -----------------
__global__ __launch_bounds__(128)
void rms_rope_kernel(float* __restrict__ x, const float* __restrict__ scale,
                     const int* __restrict__ pos, int NH) {
    const int bt = blockIdx.x / NH;
    const int h  = blockIdx.x % NH;
    float* p = x + ((size_t)bt * NH + h) * Kk;

    const int i = threadIdx.x;
    float v = p[i];

    __shared__ float red[4];
    __shared__ float sx[Kk];
    float sq = v * v;
#pragma unroll
    for (int o = 16; o; o >>= 1) sq += __shfl_xor_sync(0xffffffffu, sq, o);
    if ((i & 31) == 0) red[i >> 5] = sq;
    __syncthreads();
    float var = (red[0] + red[1] + red[2] + red[3]) * (1.0f / Kk);
    float xn  = v * rsqrtf(var + EPS) * scale[i];
    sx[i] = xn;
    __syncthreads();

    if (i < Kk / 2) {
        float x1 = sx[i];
        float x2 = sx[i + Kk / 2];
        float pp = (float)pos[bt];
        float inv = expf(-logf(ROPE_BASE) * (2.0f * (float)i / (float)Kk));
        float ang = pp * inv;
        float s, c;
        sincosf(ang, &s, &c);
        p[i]           = x1 * c - x2 * s;
        p[i + Kk / 2]  = x2 * c + x1 * s;
    }
}

// --------------------------- attention: warp per (b,t,h) ---------------------
// Contiguous key window [t - pos[t], t]; float4-vectorized K/V loads.
__global__ __launch_bounds__(256)
void attn_kernel(const float* __restrict__ q, const float* __restrict__ k,
                 const float* __restrict__ v, const int* __restrict__ pos,
                 float* __restrict__ out) {
    const int warp = threadIdx.x >> 5;
    const int lane = threadIdx.x & 31;
    const long gw = (long)blockIdx.x * 8 + warp;
    const int b = (int)(gw / ((long)Tt * Hh));
    const int rem = (int)(gw % ((long)Tt * Hh));
    const int t = rem / Hh;
    const int h = rem % Hh;
    const int g = h / Rr;

    const float4* qp = (const float4*)(q + (((size_t)b * Tt + t) * Hh + h) * Kk);
    const float4 qv = qp[lane];

    const int p  = pos[b * Tt + t];
    const int s0 = t - p;

    float m = -INFINITY, l = 0.f;
    float a0 = 0.f, a1 = 0.f, a2 = 0.f, a3 = 0.f;

    const float* kbase = k + ((size_t)b * Tt * Gg + g) * Kk;
    const float* vbase = v + ((size_t)b * Tt * Gg + g) * Kk;

    for (int s = s0; s <= t; ++s) {
        const float4 kv = *((const float4*)(kbase + (size_t)s * Gg * Kk) + lane);
        float sc = qv.x * kv.x + qv.y * kv.y + qv.z * kv.z + qv.w * kv.w;
#pragma unroll
        for (int o = 16; o; o >>= 1) sc += __shfl_xor_sync(0xffffffffu, sc, o);
        sc *= SOFTMAX_SCALE;

        float mn   = fmaxf(m, sc);
        float corr = __expf(m - mn);
        float pe   = __expf(sc - mn);
        l = l * corr + pe;

        const float4 vv = *((const float4*)(vbase + (size_t)s * Gg * Kk) + lane);
        a0 = a0 * corr + pe * vv.x;
        a1 = a1 * corr + pe * vv.y;
        a2 = a2 * corr + pe * vv.z;
        a3 = a3 * corr + pe * vv.w;
        m = mn;
    }

    float inv = 1.0f / l;
    float4* op = (float4*)(out + (((size_t)b * Tt + t) * Hh + h) * Kk);
    op[lane] = make_float4(a0 * inv, a1 * inv, a2 * inv, a3 * inv);
}

// --------------------------- launch --------------------------------------
extern "C" void kernel_launch(void* const* d_in, const int* in_sizes, int n_in,
                              void* d_out, int out_size) {
    const float* hidden  = (const float*)d_in[0];
    const float* wq      = (const float*)d_in[1];
    const float* wk      = (const float*)d_in[2];
    const float* wv      = (const float*)d_in[3];
    const float* wo      = (const float*)d_in[4];
    const float* q_scale = (const float*)d_in[5];
    const float* k_scale = (const float*)d_in[6];
    const int*   seg     = (const int*)d_in[7];
    float* out = (float*)d_out;

    float *qb, *kb, *vb, *ab;
    int* posb;
    cudaGetSymbolAddress((void**)&qb, g_q);
    cudaGetSymbolAddress((void**)&kb, g_k);
    cudaGetSymbolAddress((void**)&vb, g_v);
    cudaGetSymbolAddress((void**)&ab, g_attn);
    cudaGetSymbolAddress((void**)&posb, g_pos);

    static bool attr_set = false;
    if (!attr_set) {
        cudaFuncSetAttribute(gemm_tf32_kernel,
                             cudaFuncAttributeMaxDynamicSharedMemorySize,
                             GEMM_SMEM_BYTES);
        attr_set = true;
    }

    // 1) QKV projections (tf32 tensor cores)
    {
        dim3 blk(256);
        dim3 grdQ((Hh * Kk) / 128, MTOT / 128);
        gemm_tf32_kernel<<<grdQ, blk, GEMM_SMEM_BYTES>>>(MTOT, Hh * Kk, Dd, hidden, wq, qb);
        dim3 grdK((Gg * Kk) / 128, MTOT / 128);
        gemm_tf32_kernel<<<grdK, blk, GEMM_SMEM_BYTES>>>(MTOT, Gg * Kk, Dd, hidden, wk, kb);
        gemm_tf32_kernel<<<grdK, blk, GEMM_SMEM_BYTES>>>(MTOT, Gg * Kk, Dd, hidden, wv, vb);
    }

    // 2) positions
    pos_kernel<<<(MTOT + 255) / 256, 256>>>(seg, posb);

    // 3) RMSNorm + RoPE (in place) on q and k
    rms_rope_kernel<<<MTOT * Hh, 128>>>(qb, q_scale, posb, Hh);
    rms_rope_kernel<<<MTOT * Gg, 128>>>(kb, k_scale, posb, Gg);

    // 4) attention: one warp per (b,t,h)
    {
        long total_warps = (long)MTOT * Hh;
        int blocks = (int)(total_warps / 8);
        attn_kernel<<<blocks, 256>>>(qb, kb, vb, posb, ab);
    }

    // 5) output projection
    {
        dim3 blk(256);
        dim3 grd(Dd / 128, MTOT / 128);
        gemm_tf32_kernel<<<grd, blk, GEMM_SMEM_BYTES>>>(MTOT, Dd, Hh * Kk, ab, wo, out);
    }
}

// round 5
// speedup vs baseline: 2.1726x; 1.0018x over previous
#include <cuda_runtime.h>
#include <cuda_bf16.h>
#include <math.h>
#include <stdint.h>

// Problem constants
#define Bb 4
#define Tt 2048
#define Dd 2048
#define Hh 16
#define Gg 4
#define Kk 128
#define Rr 4          // H / G
#define EPS 1e-6f
#define ROPE_BASE 10000.0f
#define SOFTMAX_SCALE 0.08838834764831845f  // K^-0.5

#define MTOT (Bb * Tt)          // 8192 rows

// --------------------------- scratch (device globals; no mallocs) ------------
__device__ float g_q[(size_t)MTOT * Hh * Kk];     // 64 MB
__device__ float g_k[(size_t)MTOT * Gg * Kk];     // 16 MB
__device__ float g_v[(size_t)MTOT * Gg * Kk];     // 16 MB
__device__ float g_attn[(size_t)MTOT * Hh * Kk];  // 64 MB
__device__ int   g_pos[MTOT];

// =============================================================================
// TF32 tensor-core GEMM:  C[M,N] = A[M,Kd] @ B[Kd,N]   (all row-major fp32)
// CTA tile 128x128, BK=32, 256 threads (8 warps, 2x4 warp grid, warp tile 64x32)
// mma.sync.aligned.m16n8k8.row.col.f32.tf32.tf32.f32, cp.async double buffering.
// Requires M%128==0, N%128==0, Kd%32==0.
// =============================================================================
#define A_STRIDE 36            // 128 rows x 36  (pad 4) -> conflict-free A frags
#define B_STRIDE 136           // 32 rows x 136  (pad 8) -> conflict-free B frags
#define A_SZ (128 * A_STRIDE)  // floats per buffer
#define B_SZ (32 * B_STRIDE)
#define GEMM_SMEM_BYTES ((2 * A_SZ + 2 * B_SZ) * 4)   // 71680 B

__device__ __forceinline__ uint32_t f2tf32(float x) {
    uint32_t u;
    asm("cvt.rna.tf32.f32 %0, %1;" : "=r"(u) : "f"(x));
    return u;
}

__global__ __launch_bounds__(256)
void gemm_tf32_kernel(int M, int N, int Kd,
                      const float* __restrict__ A,
                      const float* __restrict__ B,
                      float* __restrict__ C) {
    extern __shared__ float sm[];
    float* As = sm;               // [2][128][A_STRIDE]
    float* Bsm = sm + 2 * A_SZ;   // [2][32][B_STRIDE]

    const int tid  = threadIdx.x;
    const int lane = tid & 31;
    const int wid  = tid >> 5;
    const int warpM = wid & 1;    // 0..1 (64 rows each)
    const int warpN = wid >> 1;   // 0..3 (32 cols each)

    const float* Ag = A + (size_t)blockIdx.y * 128 * Kd;
    const float* Bg = B + (size_t)blockIdx.x * 128;

    const uint32_t as_base = (uint32_t)__cvta_generic_to_shared(As);
    const uint32_t bs_base = (uint32_t)__cvta_generic_to_shared(Bsm);

    float acc[4][4][4];
#pragma unroll
    for (int i = 0; i < 4; i++)
#pragma unroll
        for (int j = 0; j < 4; j++)
#pragma unroll
            for (int r = 0; r < 4; r++) acc[i][j][r] = 0.f;

    auto issue_loads = [&](int buf, int k0) {
        // A tile: 128 x 32 floats, 1024 float4, 4 per thread
#pragma unroll
        for (int i = 0; i < 4; i++) {
            int idx = tid + i * 256;
            int r = idx >> 3, c = (idx & 7) * 4;
            uint32_t dst = as_base + (uint32_t)(buf * A_SZ + r * A_STRIDE + c) * 4u;
            const float* src = Ag + (size_t)r * Kd + k0 + c;
            asm volatile("cp.async.cg.shared.global [%0], [%1], 16;\n"
                         :: "r"(dst), "l"(src));
        }
        // B tile: 32 x 128 floats
#pragma unroll
        for (int i = 0; i < 4; i++) {
            int idx = tid + i * 256;
            int r = idx >> 5, c = (idx & 31) * 4;
            uint32_t dst = bs_base + (uint32_t)(buf * B_SZ + r * B_STRIDE + c) * 4u;
            const float* src = Bg + (size_t)(k0 + r) * N + c;
            asm volatile("cp.async.cg.shared.global [%0], [%1], 16;\n"
                         :: "r"(dst), "l"(src));
        }
        asm volatile("cp.async.commit_group;\n");
    };

    issue_loads(0, 0);
    const int KT = Kd >> 5;
    const int fr = lane >> 2;   // 0..7
    const int fc = lane & 3;    // 0..3

    for (int kt = 0; kt < KT; kt++) {
        asm volatile("cp.async.wait_group 0;\n");
        __syncthreads();
        const int cur = kt & 1;
        if (kt + 1 < KT) issue_loads(cur ^ 1, (kt + 1) << 5);

        const float* sA = As + cur * A_SZ;
        const float* sB = Bsm + cur * B_SZ;

#pragma unroll
        for (int kk = 0; kk < 4; kk++) {
            uint32_t af[4][4];
            uint32_t bf[4][2];
#pragma unroll
            for (int mt = 0; mt < 4; mt++) {
                const float* p = sA + (warpM * 64 + mt * 16 + fr) * A_STRIDE + kk * 8 + fc;
                af[mt][0] = f2tf32(p[0]);
                af[mt][1] = f2tf32(p[8 * A_STRIDE]);
                af[mt][2] = f2tf32(p[4]);
                af[mt][3] = f2tf32(p[8 * A_STRIDE + 4]);
            }
#pragma unroll
            for (int nt = 0; nt < 4; nt++) {
                const float* p = sB + (kk * 8 + fc) * B_STRIDE + warpN * 32 + nt * 8 + fr;
                bf[nt][0] = f2tf32(p[0]);
                bf[nt][1] = f2tf32(p[4 * B_STRIDE]);
            }
#pragma unroll
            for (int mt = 0; mt < 4; mt++)
#pragma unroll
                for (int nt = 0; nt < 4; nt++) {
                    asm volatile(
                        "mma.sync.aligned.m16n8k8.row.col.f32.tf32.tf32.f32 "
                        "{%0,%1,%2,%3}, {%4,%5,%6,%7}, {%8,%9}, {%0,%1,%2,%3};\n"
                        : "+f"(acc[mt][nt][0]), "+f"(acc[mt][nt][1]),
                          "+f"(acc[mt][nt][2]), "+f"(acc[mt][nt][3])
                        : "r"(af[mt][0]), "r"(af[mt][1]), "r"(af[mt][2]), "r"(af[mt][3]),
                          "r"(bf[nt][0]), "r"(bf[nt][1]));
                }
        }
        __syncthreads();
    }

    // Epilogue
    float* Cg = C + (size_t)blockIdx.y * 128 * N + (size_t)blockIdx.x * 128;
#pragma unroll
    for (int mt = 0; mt < 4; mt++) {
#pragma unroll
        for (int nt = 0; nt < 4; nt++) {
            int row = warpM * 64 + mt * 16 + fr;
            int col = warpN * 32 + nt * 8 + fc * 2;
            *(float2*)(Cg + (size_t)row * N + col) =
                make_float2(acc[mt][nt][0], acc[mt][nt][1]);
            *(float2*)(Cg + (size_t)(row + 8) * N + col) =
                make_float2(acc[mt][nt][2], acc[mt][nt][3]);
        }
    }
}

// --------------------------- positions from sorted segment ids ---------------
__global__ void pos_kernel(const int* __restrict__ seg, int* __restrict__ pos) {
    int idx = blockIdx.x * blockDim.x + threadIdx.x;
    if (idx >= MTOT) return;
    int b = idx / Tt;
    int t = idx % Tt;
    const int* row = seg + (size_t)b * Tt;
    int s = row[t];
    int lo = 0, hi = t;
    while (lo < hi) {
        int mid = (lo + hi) >> 1;
        if (row[mid] < s) lo = mid + 1; else hi = mid;
    }
    pos[idx] = t - lo;
}

// --------------------------- fused RMSNorm + RoPE (in place) -----------------
__global__ __launch_bounds__(128)
void rms_rope_kernel(float* __restrict__ x, const float* __restrict__ scale,
                     const int* __restrict__ pos, int NH) {
    const int bt = blockIdx.x / NH;
    const int h  = blockIdx.x % NH;
    float* p = x + ((size_t)bt * NH + h) * Kk;

    const int i = threadIdx.x;
    float v = p[i];

    __shared__ float red[4];
    __shared__ float sx[Kk];
    float sq = v * v;
#pragma unroll
    for (int o = 16; o; o >>= 1) sq += __shfl_xor_sync(0xffffffffu, sq, o);
    if ((i & 31) == 0) red[i >> 5] = sq;
    __syncthreads();
    float var = (red[0] + red[1] + red[2] + red[3]) * (1.0f / Kk);
    float xn  = v * rsqrtf(var + EPS) * scale[i];
    sx[i] = xn;
    __syncthreads();

    if (i < Kk / 2) {
        float x1 = sx[i];
        float x2 = sx[i + Kk / 2];
        float pp = (float)pos[bt];
        float inv = expf(-logf(ROPE_BASE) * (2.0f * (float)i / (float)Kk));
        float ang = pp * inv;
        float s, c;
        sincosf(ang, &s, &c);
        p[i]           = x1 * c - x2 * s;
        p[i + Kk / 2]  = x2 * c + x1 * s;
    }
}

// --------------------------- attention: warp per (b,t,h) ---------------------
// Contiguous key window [t - pos[t], t]; float4-vectorized K/V loads.
__global__ __launch_bounds__(256)
void attn_kernel(const float* __restrict__ q, const float* __restrict__ k,
                 const float* __restrict__ v, const int* __restrict__ pos,
                 float* __restrict__ out) {
    const int warp = threadIdx.x >> 5;
    const int lane = threadIdx.x & 31;
    const long gw = (long)blockIdx.x * 8 + warp;
    const int b = (int)(gw / ((long)Tt * Hh));
    const int rem = (int)(gw % ((long)Tt * Hh));
    const int t = rem / Hh;
    const int h = rem % Hh;
    const int g = h / Rr;

    const float4* qp = (const float4*)(q + (((size_t)b * Tt + t) * Hh + h) * Kk);
    const float4 qv = qp[lane];

    const int p  = pos[b * Tt + t];
    const int s0 = t - p;

    float m = -INFINITY, l = 0.f;
    float a0 = 0.f, a1 = 0.f, a2 = 0.f, a3 = 0.f;

    const float* kbase = k + ((size_t)b * Tt * Gg + g) * Kk;
    const float* vbase = v + ((size_t)b * Tt * Gg + g) * Kk;

    for (int s = s0; s <= t; ++s) {
        const float4 kv = *((const float4*)(kbase + (size_t)s * Gg * Kk) + lane);
        float sc = qv.x * kv.x + qv.y * kv.y + qv.z * kv.z + qv.w * kv.w;
#pragma unroll
        for (int o = 16; o; o >>= 1) sc += __shfl_xor_sync(0xffffffffu, sc, o);
        sc *= SOFTMAX_SCALE;

        float mn   = fmaxf(m, sc);
        float corr = __expf(m - mn);
        float pe   = __expf(sc - mn);
        l = l * corr + pe;

        const float4 vv = *((const float4*)(vbase + (size_t)s * Gg * Kk) + lane);
        a0 = a0 * corr + pe * vv.x;
        a1 = a1 * corr + pe * vv.y;
        a2 = a2 * corr + pe * vv.z;
        a3 = a3 * corr + pe * vv.w;
        m = mn;
    }

    float inv = 1.0f / l;
    float4* op = (float4*)(out + (((size_t)b * Tt + t) * Hh + h) * Kk);
    op[lane] = make_float4(a0 * inv, a1 * inv, a2 * inv, a3 * inv);
}

// --------------------------- launch --------------------------------------
extern "C" void kernel_launch(void* const* d_in, const int* in_sizes, int n_in,
                              void* d_out, int out_size) {
    const float* hidden  = (const float*)d_in[0];
    const float* wq      = (const float*)d_in[1];
    const float* wk      = (const float*)d_in[2];
    const float* wv      = (const float*)d_in[3];
    const float* wo      = (const float*)d_in[4];
    const float* q_scale = (const float*)d_in[5];
    const float* k_scale = (const float*)d_in[6];
    const int*   seg     = (const int*)d_in[7];
    float* out = (float*)d_out;

    float *qb, *kb, *vb, *ab;
    int* posb;
    cudaGetSymbolAddress((void**)&qb, g_q);
    cudaGetSymbolAddress((void**)&kb, g_k);
    cudaGetSymbolAddress((void**)&vb, g_v);
    cudaGetSymbolAddress((void**)&ab, g_attn);
    cudaGetSymbolAddress((void**)&posb, g_pos);

    static bool attr_set = false;
    if (!attr_set) {
        cudaFuncSetAttribute(gemm_tf32_kernel,
                             cudaFuncAttributeMaxDynamicSharedMemorySize,
                             GEMM_SMEM_BYTES);
        attr_set = true;
    }

    // 1) QKV projections (tf32 tensor cores)
    {
        dim3 blk(256);
        dim3 grdQ((Hh * Kk) / 128, MTOT / 128);
        gemm_tf32_kernel<<<grdQ, blk, GEMM_SMEM_BYTES>>>(MTOT, Hh * Kk, Dd, hidden, wq, qb);
        dim3 grdK((Gg * Kk) / 128, MTOT / 128);
        gemm_tf32_kernel<<<grdK, blk, GEMM_SMEM_BYTES>>>(MTOT, Gg * Kk, Dd, hidden, wk, kb);
        gemm_tf32_kernel<<<grdK, blk, GEMM_SMEM_BYTES>>>(MTOT, Gg * Kk, Dd, hidden, wv, vb);
    }

    // 2) positions
    pos_kernel<<<(MTOT + 255) / 256, 256>>>(seg, posb);

    // 3) RMSNorm + RoPE (in place) on q and k
    rms_rope_kernel<<<MTOT * Hh, 128>>>(qb, q_scale, posb, Hh);
    rms_rope_kernel<<<MTOT * Gg, 128>>>(kb, k_scale, posb, Gg);

    // 4) attention: one warp per (b,t,h)
    {
        long total_warps = (long)MTOT * Hh;
        int blocks = (int)(total_warps / 8);
        attn_kernel<<<blocks, 256>>>(qb, kb, vb, posb, ab);
    }

    // 5) output projection
    {
        dim3 blk(256);
        dim3 grd(Dd / 128, MTOT / 128);
        gemm_tf32_kernel<<<grd, blk, GEMM_SMEM_BYTES>>>(MTOT, Dd, Hh * Kk, ab, wo, out);
    }
}